// round 12
// baseline (speedup 1.0000x reference)
#include <cuda_runtime.h>

// out_matrix, label_matrix: [n, n, B] fp32, n=64, B=256.
// t(j,k) = m - (o_j-o_k)(l_j-l_k), symmetric in (j,k).
// Strict upper triangle: 2*sum relu(t) = sum t + sum |t|,
//   sum t = 2016*m - (64*sum_j o_j l_j - (sum o)(sum l))  (analytic, O(n))
// loss = [sum t + sum |t|] + B*n*n*relu(m)
// count = sum over (b,r) of [argmax_j out == argmax_j lab]
//
// Grid 256 = 64 rows x 4 batch-chunks of 64. Block 512 threads (16 warps).
// Warp w owns rows {2w, 2w+1, 62-2w, 63-2w}: 126 packed pairs, uniform.
// Argmax is 2-phase: every warp scans an 8-row segment (uniform work),
// then the two lightest warps (14,15) merge segments in ascending order.

#define NBLOCKS 256
typedef unsigned long long ull;

__device__ float    g_ploss[NBLOCKS];
__device__ int      g_pcnt[NBLOCKS];
__device__ unsigned g_done = 0;

static __device__ __forceinline__ ull add2(ull a, ull b) {
    ull d; asm("add.rn.f32x2 %0, %1, %2;" : "=l"(d) : "l"(a), "l"(b)); return d;
}
static __device__ __forceinline__ ull fma2(ull a, ull b, ull c) {
    ull d; asm("fma.rn.f32x2 %0, %1, %2, %3;" : "=l"(d) : "l"(a), "l"(b), "l"(c)); return d;
}
static __device__ __forceinline__ float2 up2(ull v) {
    float2 r; asm("mov.b64 {%0, %1}, %2;" : "=f"(r.x), "=f"(r.y) : "l"(v)); return r;
}
static __device__ __forceinline__ ull pk2(float x, float y) {
    ull v; asm("mov.b64 %0, {%1, %2};" : "=l"(v) : "f"(x), "f"(y)); return v;
}

#define SGN 0x8000000080000000ULL

// smem index of (row k, packed-batch lane p): kpair-interleaved.
#define SIDX(k, p) (((k) >> 1) * 64 + (p) * 2 + ((k) & 1))
// float index of (row k, batch b) within the packed tiles
#define FIDX(k, p, el) (2 * SIDX(k, p) + (el))

// pair core: t = m - (o_j - o_k)(l_j - l_k); acc two |t| halves (FADD |src|)
#define PAIR_ABS(ojn_, ljp_, ok_, nlk_, aX, aY) do {                      \
    const float2 t_ = up2(fma2(add2((ok_), (ojn_)), add2((ljp_), (nlk_)), m2)); \
    (aX) += fabsf(t_.x);                                                   \
    (aY) += fabsf(t_.y);                                                   \
} while (0)

__global__ void __launch_bounds__(512, 2)
fused_pair_loss_kernel(const float* __restrict__ outm,
                       const float* __restrict__ labm,
                       const float* __restrict__ marginp,
                       float* __restrict__ out, int out_size)
{
    __shared__ ull   so[64 * 32];     // packed out, kpair-interleaved  16 KB
    __shared__ ull   snl[64 * 32];    // packed -lab                    16 KB
    __shared__ float av_o[8 * 64];    // argmax seg maxima (out)         2 KB
    __shared__ float av_l[8 * 64];    // argmax seg minima (-lab)        2 KB
    __shared__ int   ai_o[8 * 64];    //                                 2 KB
    __shared__ int   ai_l[8 * 64];    //                                 2 KB
    __shared__ ull   pd_a[512];       // dot partials: -sum o*l          4 KB
    __shared__ ull   pd_b[512];       //               -sum o            4 KB
    __shared__ ull   pd_c[512];       //               +sum l            4 KB
    __shared__ float red[512];        //                                 2 KB
    __shared__ int   ired[256];       //                                 1 KB
    __shared__ int   scnt[2];
    __shared__ int   sdone;

    const int bid  = blockIdx.x;
    const int r    = bid >> 2;              // row 0..63
    const int bc   = (bid & 3) * 64;        // batch-chunk base
    const int tid  = threadIdx.x;
    const int lane = tid & 31;
    const int w    = tid >> 5;              // warp role 0..15
    const float margin = __ldg(marginp);
    const ull m2 = pk2(margin, margin);

    // Stage row r for 64 batches (kpair-interleaved, STS.128).
    for (int it = 0; it < 2; it++) {
        const int idx = tid + it * 512;          // 0..1023
        const int q = idx >> 5, p = idx & 31;    // kpair, lane
        const int g0 = (r * 64 + 2 * q) * 256 + bc + 2 * p;
        const ull o0 = *(const ull*)(outm + g0);
        const ull o1 = *(const ull*)(outm + g0 + 256);
        const ull l0 = *(const ull*)(labm + g0);
        const ull l1 = *(const ull*)(labm + g0 + 256);
        *(ulonglong2*)&so[q * 64 + p * 2]  = make_ulonglong2(o0, o1);
        *(ulonglong2*)&snl[q * 64 + p * 2] = make_ulonglong2(l0 ^ SGN, l1 ^ SGN);
    }
    __syncthreads();

    // ---- Argmax phase 1: warp w scans k-segment [8s, 8s+8), batch half h.
    {
        const int s  = w >> 1;
        const int h  = w & 1;
        const int b  = h * 32 + lane;     // batch within chunk
        const int p  = b >> 1;
        const int el = b & 1;
        const float* sof = (const float*)so;
        const float* snf = (const float*)snl;
        const int k0 = 8 * s;
        float ob = sof[FIDX(k0, p, el)]; int oi = k0;
        float lb = snf[FIDX(k0, p, el)]; int li = k0;
        #pragma unroll
        for (int d = 1; d < 8; d++) {
            const int k = k0 + d;
            const float ov = sof[FIDX(k, p, el)];
            const float lv = snf[FIDX(k, p, el)];
            if (ov > ob) { ob = ov; oi = k; }
            if (lv < lb) { lb = lv; li = k; }   // negated -> strict argmin
        }
        av_o[s * 64 + b] = ob; ai_o[s * 64 + b] = oi;
        av_l[s * 64 + b] = lb; ai_l[s * 64 + b] = li;
    }
    __syncthreads();

    // ---- Argmax phase 2: lightest warps (14,15) merge 8 segments
    // in ascending order with strict compares -> first global max.
    if (w >= 14) {
        const int b = (w - 14) * 32 + lane;
        float ob = av_o[b]; int oi = ai_o[b];
        float lb = av_l[b]; int li = ai_l[b];
        #pragma unroll
        for (int s = 1; s < 8; s++) {
            const float ov = av_o[s * 64 + b];
            const float lv = av_l[s * 64 + b];
            if (ov > ob) { ob = ov; oi = ai_o[s * 64 + b]; }
            if (lv < lb) { lb = lv; li = ai_l[s * 64 + b]; }
        }
        const unsigned ball = __ballot_sync(0xffffffffu, oi == li);
        if (lane == 0) scnt[w - 14] = __popc(ball);
    }

    // ---- Main pair loops.
    const int jl = 2 * w;
    const int jh = 62 - 2 * w;

    ull ojn[4], ljp[4];   // -o_row, +l_row for the 4 owned rows
    ojn[0] = so [SIDX(jl,     lane)] ^ SGN;
    ojn[1] = so [SIDX(jl + 1, lane)] ^ SGN;
    ojn[2] = so [SIDX(jh,     lane)] ^ SGN;
    ojn[3] = so [SIDX(jh + 1, lane)] ^ SGN;
    ljp[0] = snl[SIDX(jl,     lane)] ^ SGN;
    ljp[1] = snl[SIDX(jl + 1, lane)] ^ SGN;
    ljp[2] = snl[SIDX(jh,     lane)] ^ SGN;
    ljp[3] = snl[SIDX(jh + 1, lane)] ^ SGN;

    float a0 = 0.f, a1 = 0.f, a2 = 0.f, a3 = 0.f;
    float a4 = 0.f, a5 = 0.f, a6 = 0.f, a7 = 0.f;

    // 6 static pairs among owned rows (row[i1] < row[i2] always).
    #pragma unroll
    for (int i1 = 0; i1 < 4; i1++) {
        #pragma unroll
        for (int i2 = i1 + 1; i2 < 4; i2++) {
            const ull a = add2(ojn[i1], ojn[i2] ^ SGN);   // o_k - o_j
            const ull b = add2(ljp[i1], ljp[i2] ^ SGN);   // l_j - l_k
            const float2 t = up2(fma2(a, b, m2));
            a0 += fabsf(t.x);
            a1 += fabsf(t.y);
        }
    }

    // Per-lane dot partials for the analytic term (4 owned rows).
    ull nsol = 0, sO = 0, sL = 0;
    #pragma unroll
    for (int i = 0; i < 4; i++) {
        nsol = fma2(ojn[i], ljp[i], nsol);   // -sum o*l
        sO   = add2(sO, ojn[i]);             // -sum o
        sL   = add2(sL, ljp[i]);             // +sum l
    }

    // C: k in [jl+2, jh-1] -> pairs with the 2 low rows.
    // kpair range [w+1, 30-w], trip 30-2w (even). 4 pairs per iteration.
    {
        const ulonglong2* pso = (const ulonglong2*)&so [(w + 1) * 64 + lane * 2];
        const ulonglong2* psl = (const ulonglong2*)&snl[(w + 1) * 64 + lane * 2];
        const int trip = 30 - 2 * w;
        #pragma unroll 2
        for (int i = 0; i < trip; i++) {
            const ulonglong2 ok2 = pso[0];
            const ulonglong2 nl2 = psl[0];
            PAIR_ABS(ojn[0], ljp[0], ok2.x, nl2.x, a0, a1);
            PAIR_ABS(ojn[0], ljp[0], ok2.y, nl2.y, a2, a3);
            PAIR_ABS(ojn[1], ljp[1], ok2.x, nl2.x, a4, a5);
            PAIR_ABS(ojn[1], ljp[1], ok2.y, nl2.y, a6, a7);
            pso += 32; psl += 32;
        }
    }

    // D: k in [jh+2, 63] -> pairs with all 4 owned rows.
    // kpair range [32-w, 31], trip w. 8 pairs per iteration.
    {
        const ulonglong2* pso = (const ulonglong2*)&so [(32 - w) * 64 + lane * 2];
        const ulonglong2* psl = (const ulonglong2*)&snl[(32 - w) * 64 + lane * 2];
        const int trip = w;
        #pragma unroll 2
        for (int i = 0; i < trip; i++) {
            const ulonglong2 ok2 = pso[0];
            const ulonglong2 nl2 = psl[0];
            PAIR_ABS(ojn[0], ljp[0], ok2.x, nl2.x, a0, a1);
            PAIR_ABS(ojn[0], ljp[0], ok2.y, nl2.y, a2, a3);
            PAIR_ABS(ojn[1], ljp[1], ok2.x, nl2.x, a4, a5);
            PAIR_ABS(ojn[1], ljp[1], ok2.y, nl2.y, a6, a7);
            PAIR_ABS(ojn[2], ljp[2], ok2.x, nl2.x, a0, a1);
            PAIR_ABS(ojn[2], ljp[2], ok2.y, nl2.y, a2, a3);
            PAIR_ABS(ojn[3], ljp[3], ok2.x, nl2.x, a4, a5);
            PAIR_ABS(ojn[3], ljp[3], ok2.y, nl2.y, a6, a7);
            pso += 32; psl += 32;
        }
    }

    // ---- Reductions: one 4-sync tree covers |t| + all 3 dot partials.
    red[tid]  = ((a0 + a1) + (a2 + a3)) + ((a4 + a5) + (a6 + a7));
    pd_a[tid] = nsol; pd_b[tid] = sO; pd_c[tid] = sL;
    __syncthreads();
    if (tid < 256) {
        red[tid] += red[tid + 256];
        pd_a[tid] = add2(pd_a[tid], pd_a[tid + 256]);
        pd_b[tid] = add2(pd_b[tid], pd_b[tid + 256]);
        pd_c[tid] = add2(pd_c[tid], pd_c[tid + 256]);
    }
    __syncthreads();
    if (tid < 128) {
        red[tid] += red[tid + 128];
        pd_a[tid] = add2(pd_a[tid], pd_a[tid + 128]);
        pd_b[tid] = add2(pd_b[tid], pd_b[tid + 128]);
        pd_c[tid] = add2(pd_c[tid], pd_c[tid + 128]);
    }
    __syncthreads();
    if (tid < 64) {
        red[tid] += red[tid + 64];
        pd_a[tid] = add2(pd_a[tid], pd_a[tid + 64]);
        pd_b[tid] = add2(pd_b[tid], pd_b[tid + 64]);
        pd_c[tid] = add2(pd_c[tid], pd_c[tid + 64]);
    }
    __syncthreads();

    float bl_loss = 0.f;
    if (tid < 32) {
        const float s_abs = red[tid] + red[tid + 32];
        const ull ns = add2(pd_a[tid], pd_a[tid + 32]);
        const ull on = add2(pd_b[tid], pd_b[tid + 32]);
        const ull sl = add2(pd_c[tid], pd_c[tid + 32]);
        const ull c64   = pk2(64.f, 64.f);
        const ull m2016 = pk2(2016.f * margin, 2016.f * margin);
        ull A = fma2(c64, ns, m2016);       // 2016m - 64*sum(o*l)
        A = fma2(on ^ SGN, sl, A);          // + (sum o)(sum l)
        const float2 f = up2(A);
        float v = s_abs + (f.x + f.y);
        v += __shfl_down_sync(0xffffffffu, v, 16);
        v += __shfl_down_sync(0xffffffffu, v, 8);
        v += __shfl_down_sync(0xffffffffu, v, 4);
        v += __shfl_down_sync(0xffffffffu, v, 2);
        v += __shfl_down_sync(0xffffffffu, v, 1);
        bl_loss = v;
    }

    if (tid == 0) {
        g_ploss[bid] = bl_loss;
        g_pcnt[bid]  = scnt[0] + scnt[1];
        __threadfence();
        const unsigned t = atomicAdd(&g_done, 1u);
        sdone = (t == NBLOCKS - 1);
    }
    __syncthreads();
    if (!sdone) return;

    // Last block: deterministic final reduce over the 256 block partials.
    __threadfence();
    if (tid < 256) { red[tid] = g_ploss[tid]; ired[tid] = g_pcnt[tid]; }
    __syncthreads();
    #pragma unroll
    for (int s = 128; s > 0; s >>= 1) {
        if (tid < s) { red[tid] += red[tid + s]; ired[tid] += ired[tid + s]; }
        __syncthreads();
    }
    if (tid == 0) {
        // + diagonal: B*n*n terms of relu(margin)
        out[0] = red[0] + 1048576.f * fmaxf(margin, 0.f);
        if (out_size > 1) out[1] = (float)ired[0];
        g_done = 0;               // reset for next graph replay
    }
}

extern "C" void kernel_launch(void* const* d_in, const int* in_sizes, int n_in,
                              void* d_out, int out_size)
{
    const float* outm    = (const float*)d_in[0];
    const float* labm    = (const float*)d_in[1];
    const float* marginp = (const float*)d_in[2];
    (void)in_sizes; (void)n_in;

    fused_pair_loss_kernel<<<NBLOCKS, 512>>>(outm, labm, marginp,
                                             (float*)d_out, out_size);
}

// round 13
// speedup vs baseline: 1.0172x; 1.0172x over previous
#include <cuda_runtime.h>

// out_matrix, label_matrix: [n, n, B] fp32, n=64, B=256.
// t(j,k) = m - (o_j-o_k)(l_j-l_k), symmetric in (j,k).
// Strict upper triangle: 2*sum relu(t) = sum t + sum |t|,
//   sum t = 2016*m - (64*sum_j o_j l_j - (sum o)(sum l))  (analytic, O(n))
// loss = [sum t + sum |t|] + B*n*n*relu(m)
// count = sum over (b,r) of [argmax_j out == argmax_j lab]
//
// Grid 256 = 64 rows x 4 batch-chunks of 64. Block 512 threads (16 warps).
// Warp w owns rows {2w, 2w+1, 62-2w, 63-2w}: 126 packed pairs, uniform.
// SMEM kpair-interleaved: one LDS.128 yields 2 consecutive k (and the two
// owned row-pairs load with a single LDS.128 each).

#define NBLOCKS 256
typedef unsigned long long ull;

__device__ float    g_ploss[NBLOCKS];
__device__ int      g_pcnt[NBLOCKS];
__device__ unsigned g_done = 0;

static __device__ __forceinline__ ull add2(ull a, ull b) {
    ull d; asm("add.rn.f32x2 %0, %1, %2;" : "=l"(d) : "l"(a), "l"(b)); return d;
}
static __device__ __forceinline__ ull fma2(ull a, ull b, ull c) {
    ull d; asm("fma.rn.f32x2 %0, %1, %2, %3;" : "=l"(d) : "l"(a), "l"(b), "l"(c)); return d;
}
static __device__ __forceinline__ float2 up2(ull v) {
    float2 r; asm("mov.b64 {%0, %1}, %2;" : "=f"(r.x), "=f"(r.y) : "l"(v)); return r;
}
static __device__ __forceinline__ ull pk2(float x, float y) {
    ull v; asm("mov.b64 %0, {%1, %2};" : "=l"(v) : "f"(x), "f"(y)); return v;
}

#define SGN 0x8000000080000000ULL

// smem index of (row k, packed-batch lane p): kpair-interleaved.
#define SIDX(k, p) (((k) >> 1) * 64 + (p) * 2 + ((k) & 1))
// float index of (row k, batch b) within the packed tiles
#define FIDX(k, p, el) (2 * SIDX(k, p) + (el))

// pair core: t = m - (o_j - o_k)(l_j - l_k); acc two |t| halves (FADD |src|)
#define PAIR_ABS(ojn_, ljp_, ok_, nlk_, aX, aY) do {                      \
    const float2 t_ = up2(fma2(add2((ok_), (ojn_)), add2((ljp_), (nlk_)), m2)); \
    (aX) += fabsf(t_.x);                                                   \
    (aY) += fabsf(t_.y);                                                   \
} while (0)

__global__ void __launch_bounds__(512, 2)
fused_pair_loss_kernel(const float* __restrict__ outm,
                       const float* __restrict__ labm,
                       const float* __restrict__ marginp,
                       float* __restrict__ out, int out_size)
{
    __shared__ ull   so[64 * 32];     // packed out, kpair-interleaved  16 KB
    __shared__ ull   snl[64 * 32];    // packed -lab                    16 KB
    __shared__ float av_o[8 * 64];    // argmax seg maxima (out)         2 KB
    __shared__ float av_l[8 * 64];    // argmax seg minima (-lab)        2 KB
    __shared__ int   ai_o[8 * 64];
    __shared__ int   ai_l[8 * 64];
    __shared__ ull   pd_a[512];       // dot partials: -sum o*l
    __shared__ ull   pd_b[512];       //               -sum o
    __shared__ ull   pd_c[512];       //               +sum l
    __shared__ float red[512];
    __shared__ int   ired[256];
    __shared__ int   scnt[2];
    __shared__ int   sdone;

    const int bid  = blockIdx.x;
    const int r    = bid >> 2;              // row 0..63
    const int bc   = (bid & 3) * 64;        // batch-chunk base
    const int tid  = threadIdx.x;
    const int lane = tid & 31;
    const int w    = tid >> 5;              // warp role 0..15
    const float margin = __ldg(marginp);
    const ull m2 = pk2(margin, margin);

    // Stage row r for 64 batches (kpair-interleaved, STS.128).
    for (int it = 0; it < 2; it++) {
        const int idx = tid + it * 512;          // 0..1023
        const int q = idx >> 5, p = idx & 31;    // kpair, lane
        const int g0 = (r * 64 + 2 * q) * 256 + bc + 2 * p;
        const ull o0 = *(const ull*)(outm + g0);
        const ull o1 = *(const ull*)(outm + g0 + 256);
        const ull l0 = *(const ull*)(labm + g0);
        const ull l1 = *(const ull*)(labm + g0 + 256);
        *(ulonglong2*)&so[q * 64 + p * 2]  = make_ulonglong2(o0, o1);
        *(ulonglong2*)&snl[q * 64 + p * 2] = make_ulonglong2(l0 ^ SGN, l1 ^ SGN);
    }
    __syncthreads();

    // ---- Argmax phase 1: warp w scans k-segment [8s, 8s+8), batch half h.
    {
        const int s  = w >> 1;
        const int h  = w & 1;
        const int b  = h * 32 + lane;     // batch within chunk
        const int p  = b >> 1;
        const int el = b & 1;
        const float* sof = (const float*)so;
        const float* snf = (const float*)snl;
        const int k0 = 8 * s;
        float ob = sof[FIDX(k0, p, el)]; int oi = k0;
        float lb = snf[FIDX(k0, p, el)]; int li = k0;
        #pragma unroll
        for (int d = 1; d < 8; d++) {
            const int k = k0 + d;
            const float ov = sof[FIDX(k, p, el)];
            const float lv = snf[FIDX(k, p, el)];
            if (ov > ob) { ob = ov; oi = k; }
            if (lv < lb) { lb = lv; li = k; }   // negated -> strict argmin
        }
        av_o[s * 64 + b] = ob; ai_o[s * 64 + b] = oi;
        av_l[s * 64 + b] = lb; ai_l[s * 64 + b] = li;
    }
    __syncthreads();

    // ---- Argmax phase 2: warps 14,15 merge 8 segments in ascending order
    // with strict compares -> first global max (jnp.argmax semantics).
    if (w >= 14) {
        const int b = (w - 14) * 32 + lane;
        float ob = av_o[b]; int oi = ai_o[b];
        float lb = av_l[b]; int li = ai_l[b];
        #pragma unroll
        for (int s = 1; s < 8; s++) {
            const float ov = av_o[s * 64 + b];
            const float lv = av_l[s * 64 + b];
            if (ov > ob) { ob = ov; oi = ai_o[s * 64 + b]; }
            if (lv < lb) { lb = lv; li = ai_l[s * 64 + b]; }
        }
        const unsigned ball = __ballot_sync(0xffffffffu, oi == li);
        if (lane == 0) scnt[w - 14] = __popc(ball);
    }

    // ---- Main pair loops. Owned rows: jl=2w, jl+1 (kpair w, adjacent) and
    // jh=62-2w, jh+1 (kpair 31-w, adjacent) -> 4 LDS.128 total.
    ull ojn[4], ljp[4];   // -o_row, +l_row for the 4 owned rows
    {
        const ulonglong2 rlo_o = *(const ulonglong2*)&so [ w       * 64 + lane * 2];
        const ulonglong2 rhi_o = *(const ulonglong2*)&so [(31 - w) * 64 + lane * 2];
        const ulonglong2 rlo_l = *(const ulonglong2*)&snl[ w       * 64 + lane * 2];
        const ulonglong2 rhi_l = *(const ulonglong2*)&snl[(31 - w) * 64 + lane * 2];
        ojn[0] = rlo_o.x ^ SGN;  ojn[1] = rlo_o.y ^ SGN;
        ojn[2] = rhi_o.x ^ SGN;  ojn[3] = rhi_o.y ^ SGN;
        ljp[0] = rlo_l.x ^ SGN;  ljp[1] = rlo_l.y ^ SGN;
        ljp[2] = rhi_l.x ^ SGN;  ljp[3] = rhi_l.y ^ SGN;
    }

    float a0 = 0.f, a1 = 0.f, a2 = 0.f, a3 = 0.f;
    float a4 = 0.f, a5 = 0.f, a6 = 0.f, a7 = 0.f;

    // 6 static pairs among owned rows (row[i1] < row[i2] always).
    #pragma unroll
    for (int i1 = 0; i1 < 4; i1++) {
        #pragma unroll
        for (int i2 = i1 + 1; i2 < 4; i2++) {
            const ull a = add2(ojn[i1], ojn[i2] ^ SGN);   // o_k - o_j
            const ull b = add2(ljp[i1], ljp[i2] ^ SGN);   // l_j - l_k
            const float2 t = up2(fma2(a, b, m2));
            a0 += fabsf(t.x);
            a1 += fabsf(t.y);
        }
    }

    // Per-lane dot partials for the analytic term (4 owned rows).
    ull nsol = 0, sO = 0, sL = 0;
    #pragma unroll
    for (int i = 0; i < 4; i++) {
        nsol = fma2(ojn[i], ljp[i], nsol);   // -sum o*l
        sO   = add2(sO, ojn[i]);             // -sum o
        sL   = add2(sL, ljp[i]);             // +sum l
    }

    // C: k in [jl+2, jh-1] -> pairs with the 2 low rows.
    // kpair range [w+1, 30-w], trip 30-2w (even). 4 pairs per iteration;
    // unroll 4 batches up to 8 independent LDS.128 ahead of the math.
    {
        const ulonglong2* pso = (const ulonglong2*)&so [(w + 1) * 64 + lane * 2];
        const ulonglong2* psl = (const ulonglong2*)&snl[(w + 1) * 64 + lane * 2];
        const int trip = 30 - 2 * w;
        #pragma unroll 4
        for (int i = 0; i < trip; i++) {
            const ulonglong2 ok2 = pso[0];
            const ulonglong2 nl2 = psl[0];
            PAIR_ABS(ojn[0], ljp[0], ok2.x, nl2.x, a0, a1);
            PAIR_ABS(ojn[0], ljp[0], ok2.y, nl2.y, a2, a3);
            PAIR_ABS(ojn[1], ljp[1], ok2.x, nl2.x, a4, a5);
            PAIR_ABS(ojn[1], ljp[1], ok2.y, nl2.y, a6, a7);
            pso += 32; psl += 32;
        }
    }

    // D: k in [jh+2, 63] -> pairs with all 4 owned rows.
    // kpair range [32-w, 31], trip w. 8 pairs per iteration.
    {
        const ulonglong2* pso = (const ulonglong2*)&so [(32 - w) * 64 + lane * 2];
        const ulonglong2* psl = (const ulonglong2*)&snl[(32 - w) * 64 + lane * 2];
        const int trip = w;
        #pragma unroll 2
        for (int i = 0; i < trip; i++) {
            const ulonglong2 ok2 = pso[0];
            const ulonglong2 nl2 = psl[0];
            PAIR_ABS(ojn[0], ljp[0], ok2.x, nl2.x, a0, a1);
            PAIR_ABS(ojn[0], ljp[0], ok2.y, nl2.y, a2, a3);
            PAIR_ABS(ojn[1], ljp[1], ok2.x, nl2.x, a4, a5);
            PAIR_ABS(ojn[1], ljp[1], ok2.y, nl2.y, a6, a7);
            PAIR_ABS(ojn[2], ljp[2], ok2.x, nl2.x, a0, a1);
            PAIR_ABS(ojn[2], ljp[2], ok2.y, nl2.y, a2, a3);
            PAIR_ABS(ojn[3], ljp[3], ok2.x, nl2.x, a4, a5);
            PAIR_ABS(ojn[3], ljp[3], ok2.y, nl2.y, a6, a7);
            pso += 32; psl += 32;
        }
    }

    // ---- Reductions: one 4-sync tree covers |t| + all 3 dot partials.
    red[tid]  = ((a0 + a1) + (a2 + a3)) + ((a4 + a5) + (a6 + a7));
    pd_a[tid] = nsol; pd_b[tid] = sO; pd_c[tid] = sL;
    __syncthreads();
    if (tid < 256) {
        red[tid] += red[tid + 256];
        pd_a[tid] = add2(pd_a[tid], pd_a[tid + 256]);
        pd_b[tid] = add2(pd_b[tid], pd_b[tid + 256]);
        pd_c[tid] = add2(pd_c[tid], pd_c[tid + 256]);
    }
    __syncthreads();
    if (tid < 128) {
        red[tid] += red[tid + 128];
        pd_a[tid] = add2(pd_a[tid], pd_a[tid + 128]);
        pd_b[tid] = add2(pd_b[tid], pd_b[tid + 128]);
        pd_c[tid] = add2(pd_c[tid], pd_c[tid + 128]);
    }
    __syncthreads();
    if (tid < 64) {
        red[tid] += red[tid + 64];
        pd_a[tid] = add2(pd_a[tid], pd_a[tid + 64]);
        pd_b[tid] = add2(pd_b[tid], pd_b[tid + 64]);
        pd_c[tid] = add2(pd_c[tid], pd_c[tid + 64]);
    }
    __syncthreads();

    float bl_loss = 0.f;
    if (tid < 32) {
        const float s_abs = red[tid] + red[tid + 32];
        const ull ns = add2(pd_a[tid], pd_a[tid + 32]);
        const ull on = add2(pd_b[tid], pd_b[tid + 32]);
        const ull sl = add2(pd_c[tid], pd_c[tid + 32]);
        const ull c64   = pk2(64.f, 64.f);
        const ull m2016 = pk2(2016.f * margin, 2016.f * margin);
        ull A = fma2(c64, ns, m2016);       // 2016m - 64*sum(o*l)
        A = fma2(on ^ SGN, sl, A);          // + (sum o)(sum l)
        const float2 f = up2(A);
        float v = s_abs + (f.x + f.y);
        v += __shfl_down_sync(0xffffffffu, v, 16);
        v += __shfl_down_sync(0xffffffffu, v, 8);
        v += __shfl_down_sync(0xffffffffu, v, 4);
        v += __shfl_down_sync(0xffffffffu, v, 2);
        v += __shfl_down_sync(0xffffffffu, v, 1);
        bl_loss = v;
    }

    if (tid == 0) {
        g_ploss[bid] = bl_loss;
        g_pcnt[bid]  = scnt[0] + scnt[1];
        __threadfence();
        const unsigned t = atomicAdd(&g_done, 1u);
        sdone = (t == NBLOCKS - 1);
    }
    __syncthreads();
    if (!sdone) return;

    // Last block: deterministic final reduce over the 256 block partials.
    __threadfence();
    if (tid < 256) { red[tid] = g_ploss[tid]; ired[tid] = g_pcnt[tid]; }
    __syncthreads();
    #pragma unroll
    for (int s = 128; s > 0; s >>= 1) {
        if (tid < s) { red[tid] += red[tid + s]; ired[tid] += ired[tid + s]; }
        __syncthreads();
    }
    if (tid == 0) {
        // + diagonal: B*n*n terms of relu(margin)
        out[0] = red[0] + 1048576.f * fmaxf(margin, 0.f);
        if (out_size > 1) out[1] = (float)ired[0];
        g_done = 0;               // reset for next graph replay
    }
}

extern "C" void kernel_launch(void* const* d_in, const int* in_sizes, int n_in,
                              void* d_out, int out_size)
{
    const float* outm    = (const float*)d_in[0];
    const float* labm    = (const float*)d_in[1];
    const float* marginp = (const float*)d_in[2];
    (void)in_sizes; (void)n_in;

    fused_pair_loss_kernel<<<NBLOCKS, 512>>>(outm, labm, marginp,
                                             (float*)d_out, out_size);
}

// round 14
// speedup vs baseline: 1.0194x; 1.0022x over previous
#include <cuda_runtime.h>

// out_matrix, label_matrix: [n, n, B] fp32, n=64, B=256.
// t(j,k) = m - (o_j-o_k)(l_j-l_k), symmetric in (j,k).
// Strict upper triangle: 2*sum relu(t) = sum t + sum |t|,
//   sum t = 2016*m - (64*sum_j o_j l_j - (sum o)(sum l))  (analytic, O(n))
// loss = [sum t + sum |t|] + B*n*n*relu(m)
// count = sum over (b,r) of [argmax_j out == argmax_j lab]
//
// Grid 256 = 64 rows x 4 batch-chunks of 64. Block 512 threads (16 warps).
// Row-block wb = rows {4wb..4wb+3, 60-4wb..63-4wb}; warps wb and wb+8
// share it and split its k-range (A: 124 packed pairs, B: 128).
// SMEM kpair-interleaved: one LDS.128 yields 2 consecutive k.

#define NBLOCKS 256
typedef unsigned long long ull;

__device__ float    g_ploss[NBLOCKS];
__device__ int      g_pcnt[NBLOCKS];
__device__ unsigned g_done = 0;

static __device__ __forceinline__ ull add2(ull a, ull b) {
    ull d; asm("add.rn.f32x2 %0, %1, %2;" : "=l"(d) : "l"(a), "l"(b)); return d;
}
static __device__ __forceinline__ ull fma2(ull a, ull b, ull c) {
    ull d; asm("fma.rn.f32x2 %0, %1, %2, %3;" : "=l"(d) : "l"(a), "l"(b), "l"(c)); return d;
}
static __device__ __forceinline__ float2 up2(ull v) {
    float2 r; asm("mov.b64 {%0, %1}, %2;" : "=f"(r.x), "=f"(r.y) : "l"(v)); return r;
}
static __device__ __forceinline__ ull pk2(float x, float y) {
    ull v; asm("mov.b64 %0, {%1, %2};" : "=l"(v) : "f"(x), "f"(y)); return v;
}

#define SGN 0x8000000080000000ULL

// smem index of (row k, packed-batch lane p): kpair-interleaved.
#define SIDX(k, p) (((k) >> 1) * 64 + (p) * 2 + ((k) & 1))
// float index of (row k, batch b) within the packed tiles
#define FIDX(k, p, el) (2 * SIDX(k, p) + (el))

// pair core: t = m - (o_j - o_k)(l_j - l_k); acc two |t| halves (FADD |src|)
#define PAIR_ABS(ojn_, ljp_, ok_, nlk_, aX, aY) do {                      \
    const float2 t_ = up2(fma2(add2((ok_), (ojn_)), add2((ljp_), (nlk_)), m2)); \
    (aX) += fabsf(t_.x);                                                   \
    (aY) += fabsf(t_.y);                                                   \
} while (0)

__global__ void __launch_bounds__(512, 2)
fused_pair_loss_kernel(const float* __restrict__ outm,
                       const float* __restrict__ labm,
                       const float* __restrict__ marginp,
                       float* __restrict__ out, int out_size)
{
    __shared__ ull   so[64 * 32];     // packed out, kpair-interleaved  16 KB
    __shared__ ull   snl[64 * 32];    // packed -lab                    16 KB
    __shared__ float av_o[8 * 64];    // argmax seg maxima (out)
    __shared__ float av_l[8 * 64];    // argmax seg minima (-lab)
    __shared__ int   ai_o[8 * 64];
    __shared__ int   ai_l[8 * 64];
    __shared__ ull   pd_a[512];       // dot partials: -sum o*l
    __shared__ ull   pd_b[512];       //               -sum o
    __shared__ ull   pd_c[512];       //               +sum l
    __shared__ float red[512];
    __shared__ int   ired[256];
    __shared__ int   scnt[2];
    __shared__ int   sdone;

    const int bid  = blockIdx.x;
    const int r    = bid >> 2;              // row 0..63
    const int bc   = (bid & 3) * 64;        // batch-chunk base
    const int tid  = threadIdx.x;
    const int lane = tid & 31;
    const int w    = tid >> 5;              // warp 0..15
    const float margin = __ldg(marginp);
    const ull m2 = pk2(margin, margin);

    // Stage row r for 64 batches (kpair-interleaved, STS.128).
    for (int it = 0; it < 2; it++) {
        const int idx = tid + it * 512;          // 0..1023
        const int q = idx >> 5, p = idx & 31;    // kpair, lane
        const int g0 = (r * 64 + 2 * q) * 256 + bc + 2 * p;
        const ull o0 = *(const ull*)(outm + g0);
        const ull o1 = *(const ull*)(outm + g0 + 256);
        const ull l0 = *(const ull*)(labm + g0);
        const ull l1 = *(const ull*)(labm + g0 + 256);
        *(ulonglong2*)&so[q * 64 + p * 2]  = make_ulonglong2(o0, o1);
        *(ulonglong2*)&snl[q * 64 + p * 2] = make_ulonglong2(l0 ^ SGN, l1 ^ SGN);
    }
    __syncthreads();

    // ---- Argmax phase 1: warp w scans k-segment [8s, 8s+8), batch half h.
    {
        const int s  = w >> 1;
        const int h  = w & 1;
        const int b  = h * 32 + lane;
        const int p  = b >> 1;
        const int el = b & 1;
        const float* sof = (const float*)so;
        const float* snf = (const float*)snl;
        const int k0 = 8 * s;
        float ob = sof[FIDX(k0, p, el)]; int oi = k0;
        float lb = snf[FIDX(k0, p, el)]; int li = k0;
        #pragma unroll
        for (int d = 1; d < 8; d++) {
            const int k = k0 + d;
            const float ov = sof[FIDX(k, p, el)];
            const float lv = snf[FIDX(k, p, el)];
            if (ov > ob) { ob = ov; oi = k; }
            if (lv < lb) { lb = lv; li = k; }   // negated -> strict argmin
        }
        av_o[s * 64 + b] = ob; ai_o[s * 64 + b] = oi;
        av_l[s * 64 + b] = lb; ai_l[s * 64 + b] = li;
    }
    __syncthreads();

    // ---- Argmax phase 2 on warps 12,13 (lightest roles): ascending merge,
    // strict compares -> first global max (jnp.argmax semantics).
    if (w == 12 || w == 13) {
        const int b = (w - 12) * 32 + lane;
        float ob = av_o[b]; int oi = ai_o[b];
        float lb = av_l[b]; int li = ai_l[b];
        #pragma unroll
        for (int s = 1; s < 8; s++) {
            const float ov = av_o[s * 64 + b];
            const float lv = av_l[s * 64 + b];
            if (ov > ob) { ob = ov; oi = ai_o[s * 64 + b]; }
            if (lv < lb) { lb = lv; li = ai_l[s * 64 + b]; }
        }
        const unsigned ball = __ballot_sync(0xffffffffu, oi == li);
        if (lane == 0) scnt[w - 12] = __popc(ball);
    }

    // ---- Row-block setup: warps wb and wb+8 share rows
    // {4wb..4wb+3} (kpairs 2wb, 2wb+1) and {60-4wb..63-4wb} (30-2wb, 31-2wb).
    const int wb  = w & 7;
    const int isB = w >> 3;
    const int q0  = 2 * wb;
    const int q2  = 30 - 2 * wb;

    ull ojn[8], ljp[8];   // -o_row, +l_row; idx 0..7 = ascending row order
    {
        const ulonglong2 o01 = *(const ulonglong2*)&so [ q0      * 64 + lane * 2];
        const ulonglong2 o23 = *(const ulonglong2*)&so [(q0 + 1) * 64 + lane * 2];
        const ulonglong2 o45 = *(const ulonglong2*)&so [ q2      * 64 + lane * 2];
        const ulonglong2 o67 = *(const ulonglong2*)&so [(q2 + 1) * 64 + lane * 2];
        const ulonglong2 l01 = *(const ulonglong2*)&snl[ q0      * 64 + lane * 2];
        const ulonglong2 l23 = *(const ulonglong2*)&snl[(q0 + 1) * 64 + lane * 2];
        const ulonglong2 l45 = *(const ulonglong2*)&snl[ q2      * 64 + lane * 2];
        const ulonglong2 l67 = *(const ulonglong2*)&snl[(q2 + 1) * 64 + lane * 2];
        ojn[0] = o01.x ^ SGN; ojn[1] = o01.y ^ SGN;
        ojn[2] = o23.x ^ SGN; ojn[3] = o23.y ^ SGN;
        ojn[4] = o45.x ^ SGN; ojn[5] = o45.y ^ SGN;
        ojn[6] = o67.x ^ SGN; ojn[7] = o67.y ^ SGN;
        ljp[0] = l01.x ^ SGN; ljp[1] = l01.y ^ SGN;
        ljp[2] = l23.x ^ SGN; ljp[3] = l23.y ^ SGN;
        ljp[4] = l45.x ^ SGN; ljp[5] = l45.y ^ SGN;
        ljp[6] = l67.x ^ SGN; ljp[7] = l67.y ^ SGN;
    }

    float a0 = 0.f, a1 = 0.f, a2 = 0.f, a3 = 0.f;
    float a4 = 0.f, a5 = 0.f, a6 = 0.f, a7 = 0.f;
    ull nsol = 0, sO = 0, sL = 0;

    if (!isB) {
        // 28 static pairs among the 8 owned rows (A-warp only).
        // Hoist the un-negation of the "k" row per i2.
        #pragma unroll
        for (int i2 = 1; i2 < 8; i2++) {
            const ull rawo  = ojn[i2] ^ SGN;   // +o_i2
            const ull rawnl = ljp[i2] ^ SGN;   // -l_i2
            #pragma unroll
            for (int i1 = 0; i1 < i2; i1++) {
                PAIR_ABS(ojn[i1], ljp[i1], rawo, rawnl,
                         ((i1 & 1) ? a2 : a0), ((i1 & 1) ? a3 : a1));
            }
        }
        // Dot partials over the 8 owned rows (analytic term).
        #pragma unroll
        for (int i = 0; i < 8; i++) {
            nsol = fma2(ojn[i], ljp[i], nsol);   // -sum o*l
            sO   = add2(sO, ojn[i]);             // -sum o
            sL   = add2(sL, ljp[i]);             // +sum l
        }
    }

    // k-range split between warp A (isB=0) and B (isB=1):
    //   C kpairs [2wb+2, 30-2wb), count 28-4wb, 8 pairs each
    //   D kpairs [32-2wb, 32),    count 2wb,    16 pairs each
    const int c_total = 28 - 4 * wb;
    const int cA = (c_total < 12) ? c_total : 12;
    const int dA = 6 - (cA >> 1);
    const int cs = (2 * wb + 2) + (isB ? cA : 0);
    const int ct = isB ? (c_total - cA) : cA;
    const int ds = (32 - 2 * wb) + (isB ? dA : 0);
    const int dt = isB ? (2 * wb - dA) : dA;

    // D first: needs all 8 rows live (high rows die afterwards).
    {
        const ulonglong2* pso = (const ulonglong2*)&so [ds * 64 + lane * 2];
        const ulonglong2* psl = (const ulonglong2*)&snl[ds * 64 + lane * 2];
        for (int i = 0; i < dt; i++) {
            const ulonglong2 ok2 = pso[0];
            const ulonglong2 nl2 = psl[0];
            PAIR_ABS(ojn[0], ljp[0], ok2.x, nl2.x, a0, a1);
            PAIR_ABS(ojn[0], ljp[0], ok2.y, nl2.y, a2, a3);
            PAIR_ABS(ojn[1], ljp[1], ok2.x, nl2.x, a4, a5);
            PAIR_ABS(ojn[1], ljp[1], ok2.y, nl2.y, a6, a7);
            PAIR_ABS(ojn[2], ljp[2], ok2.x, nl2.x, a0, a1);
            PAIR_ABS(ojn[2], ljp[2], ok2.y, nl2.y, a2, a3);
            PAIR_ABS(ojn[3], ljp[3], ok2.x, nl2.x, a4, a5);
            PAIR_ABS(ojn[3], ljp[3], ok2.y, nl2.y, a6, a7);
            PAIR_ABS(ojn[4], ljp[4], ok2.x, nl2.x, a0, a1);
            PAIR_ABS(ojn[4], ljp[4], ok2.y, nl2.y, a2, a3);
            PAIR_ABS(ojn[5], ljp[5], ok2.x, nl2.x, a4, a5);
            PAIR_ABS(ojn[5], ljp[5], ok2.y, nl2.y, a6, a7);
            PAIR_ABS(ojn[6], ljp[6], ok2.x, nl2.x, a0, a1);
            PAIR_ABS(ojn[6], ljp[6], ok2.y, nl2.y, a2, a3);
            PAIR_ABS(ojn[7], ljp[7], ok2.x, nl2.x, a4, a5);
            PAIR_ABS(ojn[7], ljp[7], ok2.y, nl2.y, a6, a7);
            pso += 32; psl += 32;
        }
    }

    // C: only the 4 low rows.
    {
        const ulonglong2* pso = (const ulonglong2*)&so [cs * 64 + lane * 2];
        const ulonglong2* psl = (const ulonglong2*)&snl[cs * 64 + lane * 2];
        #pragma unroll 2
        for (int i = 0; i < ct; i++) {
            const ulonglong2 ok2 = pso[0];
            const ulonglong2 nl2 = psl[0];
            PAIR_ABS(ojn[0], ljp[0], ok2.x, nl2.x, a0, a1);
            PAIR_ABS(ojn[0], ljp[0], ok2.y, nl2.y, a2, a3);
            PAIR_ABS(ojn[1], ljp[1], ok2.x, nl2.x, a4, a5);
            PAIR_ABS(ojn[1], ljp[1], ok2.y, nl2.y, a6, a7);
            PAIR_ABS(ojn[2], ljp[2], ok2.x, nl2.x, a0, a1);
            PAIR_ABS(ojn[2], ljp[2], ok2.y, nl2.y, a2, a3);
            PAIR_ABS(ojn[3], ljp[3], ok2.x, nl2.x, a4, a5);
            PAIR_ABS(ojn[3], ljp[3], ok2.y, nl2.y, a6, a7);
            pso += 32; psl += 32;
        }
    }

    // ---- Reductions: one 4-sync tree covers |t| + all 3 dot partials.
    red[tid]  = ((a0 + a1) + (a2 + a3)) + ((a4 + a5) + (a6 + a7));
    pd_a[tid] = nsol; pd_b[tid] = sO; pd_c[tid] = sL;   // zeros for B warps
    __syncthreads();
    if (tid < 256) {
        red[tid] += red[tid + 256];
        pd_a[tid] = add2(pd_a[tid], pd_a[tid + 256]);
        pd_b[tid] = add2(pd_b[tid], pd_b[tid + 256]);
        pd_c[tid] = add2(pd_c[tid], pd_c[tid + 256]);
    }
    __syncthreads();
    if (tid < 128) {
        red[tid] += red[tid + 128];
        pd_a[tid] = add2(pd_a[tid], pd_a[tid + 128]);
        pd_b[tid] = add2(pd_b[tid], pd_b[tid + 128]);
        pd_c[tid] = add2(pd_c[tid], pd_c[tid + 128]);
    }
    __syncthreads();
    if (tid < 64) {
        red[tid] += red[tid + 64];
        pd_a[tid] = add2(pd_a[tid], pd_a[tid + 64]);
        pd_b[tid] = add2(pd_b[tid], pd_b[tid + 64]);
        pd_c[tid] = add2(pd_c[tid], pd_c[tid + 64]);
    }
    __syncthreads();

    float bl_loss = 0.f;
    if (tid < 32) {
        const float s_abs = red[tid] + red[tid + 32];
        const ull ns = add2(pd_a[tid], pd_a[tid + 32]);
        const ull on = add2(pd_b[tid], pd_b[tid + 32]);
        const ull sl = add2(pd_c[tid], pd_c[tid + 32]);
        const ull c64   = pk2(64.f, 64.f);
        const ull m2016 = pk2(2016.f * margin, 2016.f * margin);
        ull A = fma2(c64, ns, m2016);       // 2016m - 64*sum(o*l)
        A = fma2(on ^ SGN, sl, A);          // + (sum o)(sum l)
        const float2 f = up2(A);
        float v = s_abs + (f.x + f.y);
        v += __shfl_down_sync(0xffffffffu, v, 16);
        v += __shfl_down_sync(0xffffffffu, v, 8);
        v += __shfl_down_sync(0xffffffffu, v, 4);
        v += __shfl_down_sync(0xffffffffu, v, 2);
        v += __shfl_down_sync(0xffffffffu, v, 1);
        bl_loss = v;
    }

    if (tid == 0) {
        g_ploss[bid] = bl_loss;
        g_pcnt[bid]  = scnt[0] + scnt[1];
        __threadfence();
        const unsigned t = atomicAdd(&g_done, 1u);
        sdone = (t == NBLOCKS - 1);
    }
    __syncthreads();
    if (!sdone) return;

    // Last block: deterministic final reduce over the 256 block partials.
    __threadfence();
    if (tid < 256) { red[tid] = g_ploss[tid]; ired[tid] = g_pcnt[tid]; }
    __syncthreads();
    #pragma unroll
    for (int s = 128; s > 0; s >>= 1) {
        if (tid < s) { red[tid] += red[tid + s]; ired[tid] += ired[tid + s]; }
        __syncthreads();
    }
    if (tid == 0) {
        // + diagonal: B*n*n terms of relu(margin)
        out[0] = red[0] + 1048576.f * fmaxf(margin, 0.f);
        if (out_size > 1) out[1] = (float)ired[0];
        g_done = 0;               // reset for next graph replay
    }
}

extern "C" void kernel_launch(void* const* d_in, const int* in_sizes, int n_in,
                              void* d_out, int out_size)
{
    const float* outm    = (const float*)d_in[0];
    const float* labm    = (const float*)d_in[1];
    const float* marginp = (const float*)d_in[2];
    (void)in_sizes; (void)n_in;

    fused_pair_loss_kernel<<<NBLOCKS, 512>>>(outm, labm, marginp,
                                             (float*)d_out, out_size);
}